// round 13
// baseline (speedup 1.0000x reference)
#include <cuda_runtime.h>
#include <cuda_fp16.h>
#include <math.h>
#include <math_constants.h>
#include <stdint.h>

#define NT 4096
#define DM 1024
#define DF 2048
#define NE 8
#define MAXROWS (2*NT)
#define MAXTILES 80
#define TILEY 72

// ---------------- static device scratch ----------------
__device__ int   g_counts[NE];
__device__ int   g_cursor[NE];
__device__ int   g_offsets[NE+1];
__device__ int   g_perm[MAXROWS];
__device__ float g_rowgate[MAXROWS];
__device__ int   g_topidx[MAXROWS];
__device__ float g_gatesv[MAXROWS];
__device__ float g_imp_part[NE*NT];
__device__ float g_load_part[NE*NT];
__device__ float g_impsum[NE];
__device__ float g_loadsum[NE];
__device__ int   g_tile_e[MAXTILES];
__device__ int   g_tile_r0[MAXTILES];
__device__ int   g_tile_r1[MAXTILES];
__device__ int   g_ntiles;
__device__ __half g_Xrh[(size_t)NT * DM];          // 8 MB,  K-perm16 fp16 x
__device__ __half g_Hh[(size_t)MAXROWS * DF];      // 32 MB, K-perm16 fp16 H
__device__ __half g_w1th[(size_t)NE * DF * DM];    // 32 MB [E][N=DF][K=DM] perm16
__device__ __half g_w2th[(size_t)NE * DM * DF];    // 32 MB [E][N=DM][K=DF] perm16

// ---------------- helpers ----------------
__device__ __forceinline__ uint32_t smem_u32(const void* p) {
    uint32_t r;
    asm("{ .reg .u64 t; cvta.to.shared.u64 t, %1; cvt.u32.u64 %0, t; }" : "=r"(r) : "l"(p));
    return r;
}
// within each 16-group, memory order [0,1,8,9, 2,3,10,11, 4,5,12,13, 6,7,14,15]:
// lane lk's fp16 fragment halves (2lk,2lk+1,2lk+8,2lk+9) are 8 contiguous bytes.
__device__ __forceinline__ int permk16(int k) {
    int r = k & 15, m = r & 7, h = (r >> 3) & 1;
    return (k & ~15) + (m >> 1) * 4 + h * 2 + (m & 1);
}
__device__ __forceinline__ void mma_f16(float* c, uint32_t a0, uint32_t a1,
                                        uint32_t a2, uint32_t a3,
                                        uint32_t b0, uint32_t b1) {
    asm volatile("mma.sync.aligned.m16n8k16.row.col.f32.f16.f16.f32 "
        "{%0,%1,%2,%3}, {%4,%5,%6,%7}, {%8,%9}, {%0,%1,%2,%3};"
        : "+f"(c[0]), "+f"(c[1]), "+f"(c[2]), "+f"(c[3])
        : "r"(a0), "r"(a1), "r"(a2), "r"(a3), "r"(b0), "r"(b1));
}

// ---------------- reset ----------------
__global__ void reset_kernel() {
    int i = threadIdx.x;
    if (i < NE) { g_counts[i] = 0; g_cursor[i] = 0; }
}

// ---------------- fused prep: gating (blocks 0..511) + weight transpose (rest) -------
// gating: 8 warps/block, one token per warp (identical math to R8 gating).
// transpose: 32x32 tile per block; z = layer (0..7 w1, 8..15 w2).
#define GATE_BLOCKS 512
#define TRANS_BLOCKS (16 * 64 * 32)
#define PREP_BLOCKS (GATE_BLOCKS + TRANS_BLOCKS)

__global__ void __launch_bounds__(256)
prep_kernel(const float* __restrict__ x,
            const float* __restrict__ noise,
            const float* __restrict__ wg,
            const float* __restrict__ wn,
            const float* __restrict__ W1,
            const float* __restrict__ W2)
{
    __shared__ float tbuf[32][33];
    const int blk = blockIdx.x;
    const int tid = threadIdx.x;

    if (blk >= GATE_BLOCKS) {
        // ---- transpose path ----
        const int j = blk - GATE_BLOCKS;
        const int z = j >> 11;            // /2048
        const int rem = j & 2047;
        const int bx = rem & 63;
        const int by = rem >> 6;          // 0..31
        const bool one = z < 8;
        const int e = one ? z : (z - 8);
        const int K = one ? DM : DF;
        const int N = one ? DF : DM;
        const float* Wp = (one ? W1 : W2) + (size_t)e * K * N;
        __half* Wo = (one ? g_w1th : g_w2th) + (size_t)e * K * N;
        const int n0 = (one ? bx : by) * 32;
        const int k0 = (one ? by : bx) * 32;
        const int tx = tid & 31, ty = tid >> 5;
        #pragma unroll
        for (int i = 0; i < 32; i += 8)
            tbuf[ty + i][tx] = Wp[(size_t)(k0 + ty + i) * N + n0 + tx];
        __syncthreads();
        #pragma unroll
        for (int i = 0; i < 32; i += 8)
            Wo[(size_t)(n0 + ty + i) * K + permk16(k0 + tx)] = __float2half_rn(tbuf[tx][ty + i]);
        return;
    }

    // ---- gating path ----
    const int wid = tid >> 5;
    const int lane = tid & 31;
    const int t = blk * 8 + wid;

    float cg[NE], ng[NE];
    #pragma unroll
    for (int e = 0; e < NE; e++) { cg[e] = 0.f; ng[e] = 0.f; }

    const float* xr = x + (size_t)t * DM;
    __half* xo = g_Xrh + (size_t)t * DM;
    for (int k = lane; k < DM; k += 32) {
        float xv = xr[k];
        xo[permk16(k)] = __float2half_rn(xv);
        const float4* wg4 = (const float4*)(wg + (size_t)k * NE);
        const float4* wn4 = (const float4*)(wn + (size_t)k * NE);
        float4 a = wg4[0], b = wg4[1];
        float4 c = wn4[0], d = wn4[1];
        cg[0] = fmaf(xv, a.x, cg[0]); cg[1] = fmaf(xv, a.y, cg[1]);
        cg[2] = fmaf(xv, a.z, cg[2]); cg[3] = fmaf(xv, a.w, cg[3]);
        cg[4] = fmaf(xv, b.x, cg[4]); cg[5] = fmaf(xv, b.y, cg[5]);
        cg[6] = fmaf(xv, b.z, cg[6]); cg[7] = fmaf(xv, b.w, cg[7]);
        ng[0] = fmaf(xv, c.x, ng[0]); ng[1] = fmaf(xv, c.y, ng[1]);
        ng[2] = fmaf(xv, c.z, ng[2]); ng[3] = fmaf(xv, c.w, ng[3]);
        ng[4] = fmaf(xv, d.x, ng[4]); ng[5] = fmaf(xv, d.y, ng[5]);
        ng[6] = fmaf(xv, d.z, ng[6]); ng[7] = fmaf(xv, d.w, ng[7]);
    }
    #pragma unroll
    for (int e = 0; e < NE; e++) {
        #pragma unroll
        for (int o = 16; o > 0; o >>= 1) {
            cg[e] += __shfl_xor_sync(0xFFFFFFFFu, cg[e], o);
            ng[e] += __shfl_xor_sync(0xFFFFFFFFu, ng[e], o);
        }
    }

    if (lane == 0) {
        float clean[NE], stdv[NE], noisy[NE];
        #pragma unroll
        for (int e = 0; e < NE; e++) {
            clean[e] = cg[e];
            float v = ng[e];
            float sp = fmaxf(v, 0.f) + log1pf(expf(-fabsf(v)));
            stdv[e]  = sp + 0.01f;
            noisy[e] = clean[e] + noise[(size_t)t * NE + e] * stdv[e];
        }
        int i0 = 0, i1 = -1;
        float v0 = -CUDART_INF_F, v1 = -CUDART_INF_F, v2 = -CUDART_INF_F;
        #pragma unroll
        for (int e = 0; e < NE; e++) if (noisy[e] > v0) { v0 = noisy[e]; i0 = e; }
        #pragma unroll
        for (int e = 0; e < NE; e++) if (e != i0 && noisy[e] > v1) { v1 = noisy[e]; i1 = e; }
        #pragma unroll
        for (int e = 0; e < NE; e++) if (e != i0 && e != i1 && noisy[e] > v2) v2 = noisy[e];

        float d = expf(v1 - v0);
        float g0 = 1.f / (1.f + d);
        float g1 = d / (1.f + d);

        g_topidx[2*t]   = i0;  g_topidx[2*t+1] = i1;
        g_gatesv[2*t]   = g0;  g_gatesv[2*t+1] = g1;
        atomicAdd(&g_counts[i0], 1);
        atomicAdd(&g_counts[i1], 1);

        #pragma unroll
        for (int e = 0; e < NE; e++) {
            bool is_in = noisy[e] > v2;
            float thr  = is_in ? v2 : v1;
            float p = normcdff((clean[e] - thr) / stdv[e]);
            g_load_part[e*NT + t] = p;
            g_imp_part[e*NT + t]  = (e == i0) ? g0 : ((e == i1) ? g1 : 0.f);
        }
    }
}

// ---------------- meta: 128-row tiles ----------------
__global__ void meta_kernel() {
    if (threadIdx.x != 0 || blockIdx.x != 0) return;
    int off = 0;
    for (int e = 0; e < NE; e++) { g_offsets[e] = off; off += g_counts[e]; }
    g_offsets[NE] = off;
    int nt = 0;
    for (int e = 0; e < NE; e++) {
        int c = g_counts[e], base = g_offsets[e];
        for (int r = 0; r < c; r += 128) {
            g_tile_e[nt]  = e;
            g_tile_r0[nt] = base + r;
            g_tile_r1[nt] = base + ((r + 128 < c) ? (r + 128) : c);
            nt++;
        }
    }
    g_ntiles = nt;
}

// ---------------- scatter ----------------
__global__ void scatter_kernel() {
    int t = blockIdx.x * blockDim.x + threadIdx.x;
    if (t >= NT) return;
    #pragma unroll
    for (int j = 0; j < 2; j++) {
        int e = g_topidx[2*t + j];
        int p = atomicAdd(&g_cursor[e], 1);
        int row = g_offsets[e] + p;
        g_perm[row]    = t;
        g_rowgate[row] = g_gatesv[2*t + j];
    }
}

// ---------------- fp16 mma.sync grouped GEMM (R8-proven config) ----------------
// CTA: 128 grouped rows x 128 cols. 8 warps 2(m) x 4(n), warp tile 64x32.
// 2-stage double buffer, K-chunk 64 halves/stage. RSH=80 halves (160B) row pad:
// fragment LDS.64 conflict-free (row stride 40 words == 8 mod 32).
#define RSH 80
#define ASTH (128*RSH)
#define STFH (2*ASTH)
#define GEMM_SMEM (2 * STFH * 2)       // 81920 bytes

template<bool FFN1>
__global__ void __launch_bounds__(256, 2)
mma_ffn_kernel(const float* __restrict__ bias, float* __restrict__ out)
{
    constexpr int KTOT = FFN1 ? DM : DF;
    constexpr int NTOT = FFN1 ? DF : DM;
    constexpr int NS   = KTOT / 64;

    int tile = blockIdx.y;
    if (tile >= g_ntiles) return;
    const int e  = g_tile_e[tile];
    const int r0 = g_tile_r0[tile];
    const int r1 = g_tile_r1[tile];
    const int n0 = blockIdx.x * 128;

    const __half* Abase = FFN1 ? g_Xrh : g_Hh;
    const __half* Wt    = FFN1 ? g_w1th : g_w2th;

    extern __shared__ __half smh[];
    const uint32_t smb = smem_u32(smh);

    const int tid = threadIdx.x;
    const int wid = tid >> 5;
    const int lane = tid & 31;
    const int warp_m = wid >> 2;   // 0..1
    const int warp_n = wid & 3;    // 0..3
    const int lm = lane >> 2;      // 0..7
    const int lk = lane & 3;       // 0..3

    const __half* src[8]; uint32_t sz[8]; uint32_t dst[8];
    #pragma unroll
    for (int i = 0; i < 8; i++) {
        int idx = tid + i * 256;
        if (idx < 1024) {
            int row = idx >> 3, ch = idx & 7;
            int gr = r0 + row;
            bool v = gr < r1;
            size_t ar = FFN1 ? (v ? (size_t)g_perm[gr] : 0) : (v ? (size_t)gr : 0);
            src[i] = Abase + ar * KTOT + ch * 8;
            sz[i]  = v ? 16u : 0u;
            dst[i] = smb + (uint32_t)(row * RSH + ch * 8) * 2u;
        } else {
            int j = idx - 1024;
            int row = j >> 3, ch = j & 7;
            src[i] = Wt + ((size_t)e * NTOT + (size_t)(n0 + row)) * KTOT + ch * 8;
            sz[i]  = 16u;
            dst[i] = smb + (uint32_t)(ASTH + row * RSH + ch * 8) * 2u;
        }
    }

    float acc[4][4][4];
    #pragma unroll
    for (int a = 0; a < 4; a++)
        #pragma unroll
        for (int b = 0; b < 4; b++)
            #pragma unroll
            for (int c = 0; c < 4; c++) acc[a][b][c] = 0.f;

    #pragma unroll
    for (int i = 0; i < 8; i++)
        asm volatile("cp.async.cg.shared.global [%0], [%1], 16, %2;"
                     :: "r"(dst[i]), "l"(src[i]), "r"(sz[i]) : "memory");
    asm volatile("cp.async.commit_group;" ::: "memory");

    for (int s = 0; s < NS; s++) {
        asm volatile("cp.async.wait_group 0;" ::: "memory");
        __syncthreads();

        if (s + 1 < NS) {
            uint32_t so = (uint32_t)(((s + 1) & 1) * STFH * 2);
            int k0 = (s + 1) * 64;
            #pragma unroll
            for (int i = 0; i < 8; i++)
                asm volatile("cp.async.cg.shared.global [%0], [%1], 16, %2;"
                             :: "r"(dst[i] + so), "l"(src[i] + k0), "r"(sz[i]) : "memory");
            asm volatile("cp.async.commit_group;" ::: "memory");
        }

        const __half* A = smh + (s & 1) * STFH;
        const __half* B = A + ASTH;

        #pragma unroll
        for (int kk = 0; kk < 4; kk++) {
            const int ko = kk * 16 + lk * 4;
            uint32_t af[4][4], bf[4][2];
            #pragma unroll
            for (int mt = 0; mt < 4; mt++) {
                int r = warp_m * 64 + mt * 16 + lm;
                uint2 p0 = *(const uint2*)(A + r * RSH + ko);
                uint2 p1 = *(const uint2*)(A + (r + 8) * RSH + ko);
                af[mt][0] = p0.x; af[mt][2] = p0.y;
                af[mt][1] = p1.x; af[mt][3] = p1.y;
            }
            #pragma unroll
            for (int nt = 0; nt < 4; nt++) {
                int c = warp_n * 32 + nt * 8 + lm;
                uint2 pb = *(const uint2*)(B + c * RSH + ko);
                bf[nt][0] = pb.x; bf[nt][1] = pb.y;
            }
            #pragma unroll
            for (int mt = 0; mt < 4; mt++)
                #pragma unroll
                for (int nt = 0; nt < 4; nt++)
                    mma_f16(acc[mt][nt], af[mt][0], af[mt][1], af[mt][2], af[mt][3],
                            bf[nt][0], bf[nt][1]);
        }
    }

    // ---- epilogue ----
    #pragma unroll
    for (int mt = 0; mt < 4; mt++) {
        #pragma unroll
        for (int nt = 0; nt < 4; nt++) {
            int c0 = n0 + warp_n * 32 + nt * 8 + 2 * lk;   // even
            float b0 = bias[(size_t)e * NTOT + c0];
            float b1 = bias[(size_t)e * NTOT + c0 + 1];
            #pragma unroll
            for (int h = 0; h < 2; h++) {
                int row = warp_m * 64 + mt * 16 + lm + h * 8;
                int gr = r0 + row;
                if (gr >= r1) continue;
                float v0 = acc[mt][nt][2*h + 0] + b0;
                float v1 = acc[mt][nt][2*h + 1] + b1;
                if (FFN1) {
                    int m = c0 & 7, hb = (c0 >> 3) & 1;
                    int pos = (c0 & ~15) + (m >> 1) * 4 + hb * 2;
                    __half2 hv = __floats2half2_rn(fmaxf(v0, 0.f), fmaxf(v1, 0.f));
                    *(__half2*)(g_Hh + (size_t)gr * DF + pos) = hv;
                } else {
                    float gate = g_rowgate[gr];
                    float* o = out + (size_t)g_perm[gr] * DM;
                    atomicAdd(o + c0,     v0 * gate);
                    atomicAdd(o + c0 + 1, v1 * gate);
                }
            }
        }
    }
}

// ---------------- eps fixup: combined[combined==0] = eps ----------------
__global__ void eps_kernel(float* __restrict__ out) {
    int idx = blockIdx.x * blockDim.x + threadIdx.x;
    float v = out[idx];
    if (v == 0.0f) out[idx] = 2.2204460492503131e-16f;
}

// ---------------- loss ----------------
__global__ void reduce_kernel() {
    int e = blockIdx.x;
    __shared__ float sl[256], si[256];
    float a = 0.f, b = 0.f;
    for (int i = threadIdx.x; i < NT; i += 256) {
        a += g_load_part[e*NT + i];
        b += g_imp_part[e*NT + i];
    }
    sl[threadIdx.x] = a; si[threadIdx.x] = b;
    __syncthreads();
    for (int s = 128; s > 0; s >>= 1) {
        if (threadIdx.x < s) {
            sl[threadIdx.x] += sl[threadIdx.x + s];
            si[threadIdx.x] += si[threadIdx.x + s];
        }
        __syncthreads();
    }
    if (threadIdx.x == 0) { g_loadsum[e] = sl[0]; g_impsum[e] = si[0]; }
}

__global__ void loss_kernel(float* __restrict__ out, int out_size) {
    if (threadIdx.x != 0 || blockIdx.x != 0) return;
    float mi = 0.f, ml = 0.f;
    for (int e = 0; e < NE; e++) { mi += g_impsum[e]; ml += g_loadsum[e]; }
    mi *= (1.f / NE); ml *= (1.f / NE);
    float vi = 0.f, vl = 0.f;
    for (int e = 0; e < NE; e++) {
        float di = g_impsum[e] - mi; vi += di * di;
        float dl = g_loadsum[e] - ml; vl += dl * dl;
    }
    vi /= (float)(NE - 1);
    vl /= (float)(NE - 1);
    float loss = 0.1f * (vi / (mi*mi + 1e-10f) + vl / (ml*ml + 1e-10f));
    out[out_size - 1] = loss;
}

// ---------------- launch ----------------
extern "C" void kernel_launch(void* const* d_in, const int* in_sizes, int n_in,
                              void* d_out, int out_size) {
    const float* x     = (const float*)d_in[0];
    const float* noise = (const float*)d_in[1];
    const float* wg    = (const float*)d_in[2];
    const float* wn    = (const float*)d_in[3];
    const float* w1    = (const float*)d_in[4];
    const float* b1    = (const float*)d_in[5];
    const float* w2    = (const float*)d_in[6];
    const float* b2    = (const float*)d_in[7];
    float* out = (float*)d_out;

    cudaFuncSetAttribute(mma_ffn_kernel<true>,
                         cudaFuncAttributeMaxDynamicSharedMemorySize, GEMM_SMEM);
    cudaFuncSetAttribute(mma_ffn_kernel<false>,
                         cudaFuncAttributeMaxDynamicSharedMemorySize, GEMM_SMEM);

    cudaMemsetAsync(out, 0, (size_t)out_size * sizeof(float));
    reset_kernel<<<1, 32>>>();
    prep_kernel<<<PREP_BLOCKS, 256>>>(x, noise, wg, wn, w1, w2);
    meta_kernel<<<1, 1>>>();
    scatter_kernel<<<NT/256, 256>>>();

    mma_ffn_kernel<true ><<<dim3(DF/128, TILEY), 256, GEMM_SMEM>>>(b1, nullptr);
    mma_ffn_kernel<false><<<dim3(DM/128, TILEY), 256, GEMM_SMEM>>>(b2, out);

    eps_kernel<<<(NT*DM)/256, 256>>>(out);
    reduce_kernel<<<NE, 256>>>();
    loss_kernel<<<1, 32>>>(out, out_size);
}

// round 14
// speedup vs baseline: 1.0468x; 1.0468x over previous
#include <cuda_runtime.h>
#include <cuda_fp16.h>
#include <math.h>
#include <math_constants.h>
#include <stdint.h>

#define NT 4096
#define DM 1024
#define DF 2048
#define NE 8
#define MAXROWS (2*NT)
#define MAXTILES 80
#define TILEY 72

// ---------------- static device scratch ----------------
__device__ int   g_counts[NE];
__device__ int   g_cursor[NE];
__device__ int   g_offsets[NE+1];
__device__ int   g_perm[MAXROWS];
__device__ float g_rowgate[MAXROWS];
__device__ int   g_topidx[MAXROWS];
__device__ float g_gatesv[MAXROWS];
__device__ float g_imp_part[NE*NT];
__device__ float g_load_part[NE*NT];
__device__ float g_impsum[NE];
__device__ float g_loadsum[NE];
__device__ int   g_tile_e[MAXTILES];
__device__ int   g_tile_r0[MAXTILES];
__device__ int   g_tile_r1[MAXTILES];
__device__ int   g_ntiles;
__device__ int   g_fin;
__device__ float g_wgT[NE*DM];                     // [e][k] transposed gate weights
__device__ float g_wnT[NE*DM];
__device__ __half g_Xrh[(size_t)NT * DM];          // 8 MB,  K-perm16 fp16 x
__device__ __half g_Hh[(size_t)MAXROWS * DF];      // 32 MB, K-perm16 fp16 H
__device__ __half g_w1th[(size_t)NE * DF * DM];    // 32 MB [E][N=DF][K=DM] perm16
__device__ __half g_w2th[(size_t)NE * DM * DF];    // 32 MB [E][N=DM][K=DF] perm16

// ---------------- helpers ----------------
__device__ __forceinline__ uint32_t smem_u32(const void* p) {
    uint32_t r;
    asm("{ .reg .u64 t; cvta.to.shared.u64 t, %1; cvt.u32.u64 %0, t; }" : "=r"(r) : "l"(p));
    return r;
}
// within each 16-group, memory order [0,1,8,9, 2,3,10,11, 4,5,12,13, 6,7,14,15]:
// lane lk's fp16 fragment halves (2lk,2lk+1,2lk+8,2lk+9) are 8 contiguous bytes.
__device__ __forceinline__ int permk16(int k) {
    int r = k & 15, m = r & 7, h = (r >> 3) & 1;
    return (k & ~15) + (m >> 1) * 4 + h * 2 + (m & 1);
}
__device__ __forceinline__ void mma_f16(float* c, uint32_t a0, uint32_t a1,
                                        uint32_t a2, uint32_t a3,
                                        uint32_t b0, uint32_t b1) {
    asm volatile("mma.sync.aligned.m16n8k16.row.col.f32.f16.f16.f32 "
        "{%0,%1,%2,%3}, {%4,%5,%6,%7}, {%8,%9}, {%0,%1,%2,%3};"
        : "+f"(c[0]), "+f"(c[1]), "+f"(c[2]), "+f"(c[3])
        : "r"(a0), "r"(a1), "r"(a2), "r"(a3), "r"(b0), "r"(b1));
}

// ---------------- reset + gate-weight transpose ----------------
// 32 blocks x 256 thr: each thread moves one element of wg and wn into [e][k] layout.
__global__ void reset_kernel(const float* __restrict__ wg, const float* __restrict__ wn) {
    int j = blockIdx.x * 256 + threadIdx.x;      // 0..8191
    int e = j >> 10, k = j & 1023;
    g_wgT[j] = wg[k * NE + e];
    g_wnT[j] = wn[k * NE + e];
    if (blockIdx.x == 0 && threadIdx.x < NE) {
        g_counts[threadIdx.x] = 0;
        g_cursor[threadIdx.x] = 0;
    }
    if (blockIdx.x == 0 && threadIdx.x == NE) g_fin = 0;
}

// ---------------- gating: one warp per token; coalesced [e][k] weight reads ----------
// Per-lane k assignment and FMA order identical to the R8/R12 version (bit-exact).
__global__ void gating_kernel(const float* __restrict__ x,
                              const float* __restrict__ noise)
{
    int warp = (blockIdx.x * blockDim.x + threadIdx.x) >> 5;
    int lane = threadIdx.x & 31;
    if (warp >= NT) return;
    const int t = warp;

    float cg[NE], ng[NE];
    #pragma unroll
    for (int e = 0; e < NE; e++) { cg[e] = 0.f; ng[e] = 0.f; }

    const float* xr = x + (size_t)t * DM;
    __half* xo = g_Xrh + (size_t)t * DM;
    for (int k = lane; k < DM; k += 32) {
        float xv = xr[k];
        xo[permk16(k)] = __float2half_rn(xv);
        #pragma unroll
        for (int e = 0; e < NE; e++) {
            cg[e] = fmaf(xv, g_wgT[e * DM + k], cg[e]);
            ng[e] = fmaf(xv, g_wnT[e * DM + k], ng[e]);
        }
    }
    #pragma unroll
    for (int e = 0; e < NE; e++) {
        #pragma unroll
        for (int o = 16; o > 0; o >>= 1) {
            cg[e] += __shfl_xor_sync(0xFFFFFFFFu, cg[e], o);
            ng[e] += __shfl_xor_sync(0xFFFFFFFFu, ng[e], o);
        }
    }

    if (lane == 0) {
        float clean[NE], stdv[NE], noisy[NE];
        #pragma unroll
        for (int e = 0; e < NE; e++) {
            clean[e] = cg[e];
            float v = ng[e];
            float sp = fmaxf(v, 0.f) + log1pf(expf(-fabsf(v)));
            stdv[e]  = sp + 0.01f;
            noisy[e] = clean[e] + noise[(size_t)t * NE + e] * stdv[e];
        }
        int i0 = 0, i1 = -1;
        float v0 = -CUDART_INF_F, v1 = -CUDART_INF_F, v2 = -CUDART_INF_F;
        #pragma unroll
        for (int e = 0; e < NE; e++) if (noisy[e] > v0) { v0 = noisy[e]; i0 = e; }
        #pragma unroll
        for (int e = 0; e < NE; e++) if (e != i0 && noisy[e] > v1) { v1 = noisy[e]; i1 = e; }
        #pragma unroll
        for (int e = 0; e < NE; e++) if (e != i0 && e != i1 && noisy[e] > v2) v2 = noisy[e];

        float d = expf(v1 - v0);
        float g0 = 1.f / (1.f + d);
        float g1 = d / (1.f + d);

        g_topidx[2*t]   = i0;  g_topidx[2*t+1] = i1;
        g_gatesv[2*t]   = g0;  g_gatesv[2*t+1] = g1;
        atomicAdd(&g_counts[i0], 1);
        atomicAdd(&g_counts[i1], 1);

        #pragma unroll
        for (int e = 0; e < NE; e++) {
            bool is_in = noisy[e] > v2;
            float thr  = is_in ? v2 : v1;
            float p = normcdff((clean[e] - thr) / stdv[e]);
            g_load_part[e*NT + t] = p;
            g_imp_part[e*NT + t]  = (e == i0) ? g0 : ((e == i1) ? g1 : 0.f);
        }
    }
}

// ---------------- meta: 128-row tiles ----------------
__global__ void meta_kernel() {
    if (threadIdx.x != 0 || blockIdx.x != 0) return;
    int off = 0;
    for (int e = 0; e < NE; e++) { g_offsets[e] = off; off += g_counts[e]; }
    g_offsets[NE] = off;
    int nt = 0;
    for (int e = 0; e < NE; e++) {
        int c = g_counts[e], base = g_offsets[e];
        for (int r = 0; r < c; r += 128) {
            g_tile_e[nt]  = e;
            g_tile_r0[nt] = base + r;
            g_tile_r1[nt] = base + ((r + 128 < c) ? (r + 128) : c);
            nt++;
        }
    }
    g_ntiles = nt;
}

// ---------------- scatter ----------------
__global__ void scatter_kernel() {
    int t = blockIdx.x * blockDim.x + threadIdx.x;
    if (t >= NT) return;
    #pragma unroll
    for (int j = 0; j < 2; j++) {
        int e = g_topidx[2*t + j];
        int p = atomicAdd(&g_cursor[e], 1);
        int row = g_offsets[e] + p;
        g_perm[row]    = t;
        g_rowgate[row] = g_gatesv[2*t + j];
    }
}

// ---------------- merged weight transpose -> fp16 perm16 ----------------
// z 0..7: w1 (x->nblk 64, y->kblk 32); z 8..15: w2 (x->kblk 64, y->nblk 32). No idle blocks.
__global__ void transpose_h_kernel(const float* __restrict__ W1,
                                   const float* __restrict__ W2)
{
    __shared__ float t[32][33];
    const bool one = blockIdx.z < 8;
    const int e = one ? blockIdx.z : (blockIdx.z - 8);
    const int K = one ? DM : DF;
    const int N = one ? DF : DM;
    const float* Wp = (one ? W1 : W2) + (size_t)e * K * N;
    __half* Wo = (one ? g_w1th : g_w2th) + (size_t)e * K * N;
    const int n0 = (one ? blockIdx.x : blockIdx.y) * 32;
    const int k0 = (one ? blockIdx.y : blockIdx.x) * 32;
    int tx = threadIdx.x, ty = threadIdx.y;
    #pragma unroll
    for (int i = 0; i < 32; i += 8)
        t[ty + i][tx] = Wp[(size_t)(k0 + ty + i) * N + n0 + tx];
    __syncthreads();
    #pragma unroll
    for (int i = 0; i < 32; i += 8)
        Wo[(size_t)(n0 + ty + i) * K + permk16(k0 + tx)] = __float2half_rn(t[tx][ty + i]);
}

// ---------------- fp16 mma.sync grouped GEMM (R8-proven config) ----------------
#define RSH 80
#define ASTH (128*RSH)
#define STFH (2*ASTH)
#define GEMM_SMEM (2 * STFH * 2)       // 81920 bytes

template<bool FFN1>
__global__ void __launch_bounds__(256, 2)
mma_ffn_kernel(const float* __restrict__ bias, float* __restrict__ out)
{
    constexpr int KTOT = FFN1 ? DM : DF;
    constexpr int NTOT = FFN1 ? DF : DM;
    constexpr int NS   = KTOT / 64;

    int tile = blockIdx.y;
    if (tile >= g_ntiles) return;
    const int e  = g_tile_e[tile];
    const int r0 = g_tile_r0[tile];
    const int r1 = g_tile_r1[tile];
    const int n0 = blockIdx.x * 128;

    const __half* Abase = FFN1 ? g_Xrh : g_Hh;
    const __half* Wt    = FFN1 ? g_w1th : g_w2th;

    extern __shared__ __half smh[];
    const uint32_t smb = smem_u32(smh);

    const int tid = threadIdx.x;
    const int wid = tid >> 5;
    const int lane = tid & 31;
    const int warp_m = wid >> 2;   // 0..1
    const int warp_n = wid & 3;    // 0..3
    const int lm = lane >> 2;      // 0..7
    const int lk = lane & 3;       // 0..3

    const __half* src[8]; uint32_t sz[8]; uint32_t dst[8];
    #pragma unroll
    for (int i = 0; i < 8; i++) {
        int idx = tid + i * 256;
        if (idx < 1024) {
            int row = idx >> 3, ch = idx & 7;
            int gr = r0 + row;
            bool v = gr < r1;
            size_t ar = FFN1 ? (v ? (size_t)g_perm[gr] : 0) : (v ? (size_t)gr : 0);
            src[i] = Abase + ar * KTOT + ch * 8;
            sz[i]  = v ? 16u : 0u;
            dst[i] = smb + (uint32_t)(row * RSH + ch * 8) * 2u;
        } else {
            int j = idx - 1024;
            int row = j >> 3, ch = j & 7;
            src[i] = Wt + ((size_t)e * NTOT + (size_t)(n0 + row)) * KTOT + ch * 8;
            sz[i]  = 16u;
            dst[i] = smb + (uint32_t)(ASTH + row * RSH + ch * 8) * 2u;
        }
    }

    float acc[4][4][4];
    #pragma unroll
    for (int a = 0; a < 4; a++)
        #pragma unroll
        for (int b = 0; b < 4; b++)
            #pragma unroll
            for (int c = 0; c < 4; c++) acc[a][b][c] = 0.f;

    #pragma unroll
    for (int i = 0; i < 8; i++)
        asm volatile("cp.async.cg.shared.global [%0], [%1], 16, %2;"
                     :: "r"(dst[i]), "l"(src[i]), "r"(sz[i]) : "memory");
    asm volatile("cp.async.commit_group;" ::: "memory");

    for (int s = 0; s < NS; s++) {
        asm volatile("cp.async.wait_group 0;" ::: "memory");
        __syncthreads();

        if (s + 1 < NS) {
            uint32_t so = (uint32_t)(((s + 1) & 1) * STFH * 2);
            int k0 = (s + 1) * 64;
            #pragma unroll
            for (int i = 0; i < 8; i++)
                asm volatile("cp.async.cg.shared.global [%0], [%1], 16, %2;"
                             :: "r"(dst[i] + so), "l"(src[i] + k0), "r"(sz[i]) : "memory");
            asm volatile("cp.async.commit_group;" ::: "memory");
        }

        const __half* A = smh + (s & 1) * STFH;
        const __half* B = A + ASTH;

        #pragma unroll
        for (int kk = 0; kk < 4; kk++) {
            const int ko = kk * 16 + lk * 4;
            uint32_t af[4][4], bf[4][2];
            #pragma unroll
            for (int mt = 0; mt < 4; mt++) {
                int r = warp_m * 64 + mt * 16 + lm;
                uint2 p0 = *(const uint2*)(A + r * RSH + ko);
                uint2 p1 = *(const uint2*)(A + (r + 8) * RSH + ko);
                af[mt][0] = p0.x; af[mt][2] = p0.y;
                af[mt][1] = p1.x; af[mt][3] = p1.y;
            }
            #pragma unroll
            for (int nt = 0; nt < 4; nt++) {
                int c = warp_n * 32 + nt * 8 + lm;
                uint2 pb = *(const uint2*)(B + c * RSH + ko);
                bf[nt][0] = pb.x; bf[nt][1] = pb.y;
            }
            #pragma unroll
            for (int mt = 0; mt < 4; mt++)
                #pragma unroll
                for (int nt = 0; nt < 4; nt++)
                    mma_f16(acc[mt][nt], af[mt][0], af[mt][1], af[mt][2], af[mt][3],
                            bf[nt][0], bf[nt][1]);
        }
    }

    // ---- epilogue ----
    #pragma unroll
    for (int mt = 0; mt < 4; mt++) {
        #pragma unroll
        for (int nt = 0; nt < 4; nt++) {
            int c0 = n0 + warp_n * 32 + nt * 8 + 2 * lk;   // even
            float b0 = bias[(size_t)e * NTOT + c0];
            float b1 = bias[(size_t)e * NTOT + c0 + 1];
            #pragma unroll
            for (int h = 0; h < 2; h++) {
                int row = warp_m * 64 + mt * 16 + lm + h * 8;
                int gr = r0 + row;
                if (gr >= r1) continue;
                float v0 = acc[mt][nt][2*h + 0] + b0;
                float v1 = acc[mt][nt][2*h + 1] + b1;
                if (FFN1) {
                    int m = c0 & 7, hb = (c0 >> 3) & 1;
                    int pos = (c0 & ~15) + (m >> 1) * 4 + hb * 2;
                    __half2 hv = __floats2half2_rn(fmaxf(v0, 0.f), fmaxf(v1, 0.f));
                    *(__half2*)(g_Hh + (size_t)gr * DF + pos) = hv;
                } else {
                    float gate = g_rowgate[gr];
                    float* o = out + (size_t)g_perm[gr] * DM;
                    atomicAdd(o + c0,     v0 * gate);
                    atomicAdd(o + c0 + 1, v1 * gate);
                }
            }
        }
    }
}

// ---------------- finish: eps fixup + loss reduction + loss (fused) ----------------
__global__ void finish_kernel(float* __restrict__ out, int out_size) {
    int idx = blockIdx.x * blockDim.x + threadIdx.x;
    float v = out[idx];
    if (v == 0.0f) out[idx] = 2.2204460492503131e-16f;

    if (blockIdx.x < NE) {
        const int e = blockIdx.x;
        __shared__ float sl[256], si[256];
        float a = 0.f, b = 0.f;
        for (int i = threadIdx.x; i < NT; i += 256) {
            a += g_load_part[e*NT + i];
            b += g_imp_part[e*NT + i];
        }
        sl[threadIdx.x] = a; si[threadIdx.x] = b;
        __syncthreads();
        for (int s = 128; s > 0; s >>= 1) {
            if (threadIdx.x < s) {
                sl[threadIdx.x] += sl[threadIdx.x + s];
                si[threadIdx.x] += si[threadIdx.x + s];
            }
            __syncthreads();
        }
        if (threadIdx.x == 0) {
            g_loadsum[e] = sl[0];
            g_impsum[e]  = si[0];
            __threadfence();
            if (atomicAdd(&g_fin, 1) == NE - 1) {
                __threadfence();
                float mi = 0.f, ml = 0.f;
                for (int k = 0; k < NE; k++) { mi += g_impsum[k]; ml += g_loadsum[k]; }
                mi *= (1.f / NE); ml *= (1.f / NE);
                float vi = 0.f, vl = 0.f;
                for (int k = 0; k < NE; k++) {
                    float di = g_impsum[k] - mi; vi += di * di;
                    float dl = g_loadsum[k] - ml; vl += dl * dl;
                }
                vi /= (float)(NE - 1);
                vl /= (float)(NE - 1);
                out[out_size - 1] = 0.1f * (vi / (mi*mi + 1e-10f) + vl / (ml*ml + 1e-10f));
            }
        }
    }
}

// ---------------- launch ----------------
extern "C" void kernel_launch(void* const* d_in, const int* in_sizes, int n_in,
                              void* d_out, int out_size) {
    const float* x     = (const float*)d_in[0];
    const float* noise = (const float*)d_in[1];
    const float* wg    = (const float*)d_in[2];
    const float* wn    = (const float*)d_in[3];
    const float* w1    = (const float*)d_in[4];
    const float* b1    = (const float*)d_in[5];
    const float* w2    = (const float*)d_in[6];
    const float* b2    = (const float*)d_in[7];
    float* out = (float*)d_out;

    cudaFuncSetAttribute(mma_ffn_kernel<true>,
                         cudaFuncAttributeMaxDynamicSharedMemorySize, GEMM_SMEM);
    cudaFuncSetAttribute(mma_ffn_kernel<false>,
                         cudaFuncAttributeMaxDynamicSharedMemorySize, GEMM_SMEM);

    cudaMemsetAsync(out, 0, (size_t)out_size * sizeof(float));
    reset_kernel<<<32, 256>>>(wg, wn);
    gating_kernel<<<NT/4, 128>>>(x, noise);
    meta_kernel<<<1, 1>>>();
    scatter_kernel<<<NT/256, 256>>>();

    transpose_h_kernel<<<dim3(64, 32, 16), dim3(32, 8)>>>(w1, w2);

    mma_ffn_kernel<true ><<<dim3(DF/128, TILEY), 256, GEMM_SMEM>>>(b1, nullptr);
    mma_ffn_kernel<false><<<dim3(DM/128, TILEY), 256, GEMM_SMEM>>>(b2, out);

    finish_kernel<<<(NT*DM)/256, 256>>>(out, out_size);
}